// round 14
// baseline (speedup 1.0000x reference)
#include <cuda_runtime.h>
#include <cuda_bf16.h>
#include <cuda_fp16.h>

typedef unsigned long long ull;
typedef unsigned int u32;

// ---------------------------------------------------------------------------
// Scratch planes (fp16): q single, k/v hi+lo, attn-out single
// ---------------------------------------------------------------------------
#define PLANE_ELEMS 33554432
static __device__ unsigned short g_qh[PLANE_ELEMS];
static __device__ unsigned short g_kh[PLANE_ELEMS], g_kl[PLANE_ELEMS];
static __device__ unsigned short g_vh[PLANE_ELEMS], g_vl[PLANE_ELEMS];
static __device__ unsigned short g_aoh[PLANE_ELEMS];

// B fragments (fp16 wh/wl), mma.sync fragment order, tap-major.
static __device__ __align__(16) uint4 g_Bfq[9 * 4 * 12 * 32];
static __device__ __align__(16) uint4 g_Bfo[9 * 2 * 8 * 32];

// ---------------------------------------------------------------------------
// helpers
// ---------------------------------------------------------------------------
__device__ __forceinline__ u32 smem_u32(const void* p) {
    u32 a;
    asm("{ .reg .u64 t; cvta.to.shared.u64 t, %1; cvt.u32.u64 %0, t; }" : "=r"(a) : "l"(p));
    return a;
}
__device__ __forceinline__ unsigned short us_hf(__half h) {
    return *reinterpret_cast<unsigned short*>(&h);
}
__device__ __forceinline__ void split_hf(float v, unsigned short& h, unsigned short& l) {
    __half hb = __float2half(v);
    h = us_hf(hb);
    l = us_hf(__float2half(v - __half2float(hb)));
}
__device__ __forceinline__ u32 hpack(float a, float b) {
    __half2 h = __floats2half2_rn(a, b);
    return *reinterpret_cast<u32*>(&h);
}
__device__ __forceinline__ void ldsm4(u32* r, u32 addr) {
    asm volatile("ldmatrix.sync.aligned.m8n8.x4.shared.b16 {%0,%1,%2,%3}, [%4];"
                 : "=r"(r[0]), "=r"(r[1]), "=r"(r[2]), "=r"(r[3]) : "r"(addr));
}
__device__ __forceinline__ void ldsm4t(u32* r, u32 addr) {
    asm volatile("ldmatrix.sync.aligned.m8n8.x4.trans.shared.b16 {%0,%1,%2,%3}, [%4];"
                 : "=r"(r[0]), "=r"(r[1]), "=r"(r[2]), "=r"(r[3]) : "r"(addr));
}
__device__ __forceinline__ void mma_fp16(float* c, const u32* a, u32 b0, u32 b1) {
    asm volatile(
        "mma.sync.aligned.m16n8k16.row.col.f32.f16.f16.f32 "
        "{%0,%1,%2,%3}, {%4,%5,%6,%7}, {%8,%9}, {%0,%1,%2,%3};"
        : "+f"(c[0]), "+f"(c[1]), "+f"(c[2]), "+f"(c[3])
        : "r"(a[0]), "r"(a[1]), "r"(a[2]), "r"(a[3]), "r"(b0), "r"(b1));
}
__device__ __forceinline__ void cpa16(u32 dst, const void* src) {
    asm volatile("cp.async.cg.shared.global [%0], [%1], 16;" :: "r"(dst), "l"(src));
}
#define CPA_COMMIT() asm volatile("cp.async.commit_group;" ::: "memory")
#define CPA_WAIT0()  asm volatile("cp.async.wait_group 0;" ::: "memory")

// ---------------------------------------------------------------------------
// Weight fragment pre-pack (fp16 wh / wl)
// ---------------------------------------------------------------------------
__global__ void pack_qkv_frag(const float* __restrict__ wq, const float* __restrict__ wk,
                              const float* __restrict__ wv)
{
    int idx = blockIdx.x * 256 + threadIdx.x;
    if (idx >= 9 * 4 * 12 * 32) return;
    int lane = idx & 31; int t = idx >> 5;
    int n8 = t % 12; t /= 12;
    int ks = t & 3;  int tap = t >> 2;
    int dh = tap / 3, dw = tap % 3;
    int n = n8 * 8 + (lane >> 2);
    const float* src = (n < 32) ? wq + n * 576
                     : (n < 64) ? wk + (n - 32) * 576
                                : wv + (n - 64) * 576;
    u32 u[4];
#pragma unroll
    for (int r = 0; r < 2; r++) {
        int ic0 = ks * 16 + r * 8 + (lane & 3) * 2;
        float w0 = src[ic0 * 9 + dh * 3 + dw];
        float w1 = src[(ic0 + 1) * 9 + dh * 3 + dw];
        unsigned short h0, l0, h1, l1;
        split_hf(w0, h0, l0); split_hf(w1, h1, l1);
        u[r]     = (u32)h0 | ((u32)h1 << 16);
        u[2 + r] = (u32)l0 | ((u32)l1 << 16);
    }
    g_Bfq[idx] = make_uint4(u[0], u[1], u[2], u[3]);
}

__global__ void pack_o_frag(const float* __restrict__ wo)
{
    int idx = blockIdx.x * 256 + threadIdx.x;
    if (idx >= 9 * 2 * 8 * 32) return;
    int lane = idx & 31; int t = idx >> 5;
    int n8 = t & 7; t >>= 3;
    int ks = t & 1;  int tap = t >> 1;
    int dh = tap / 3, dw = tap % 3;
    int n = n8 * 8 + (lane >> 2);
    const float* src = wo + n * 288;
    u32 u[4];
#pragma unroll
    for (int r = 0; r < 2; r++) {
        int ic0 = ks * 16 + r * 8 + (lane & 3) * 2;
        float w0 = src[ic0 * 9 + dh * 3 + dw];
        float w1 = src[(ic0 + 1) * 9 + dh * 3 + dw];
        unsigned short h0, l0, h1, l1;
        split_hf(w0, h0, l0); split_hf(w1, h1, l1);
        u[r]     = (u32)h0 | ((u32)h1 << 16);
        u[2 + r] = (u32)l0 | ((u32)l1 << 16);
    }
    g_Bfo[idx] = make_uint4(u[0], u[1], u[2], u[3]);
}

// ---------------------------------------------------------------------------
// qkv conv: full-frame block.  Grid (64 s, 16 b), 512 threads (16 warps).
// Halo [34*34][72] fp16 resident; loop over 8 strips of 128 pixels.
// Warp tile per strip: 32 M x 24 N (2 m16 x 3 n8).
// ---------------------------------------------------------------------------
#define QKV_HALO  166464                    // 1156 * 144 B
#define QKV_SMEM  (QKV_HALO + 50688)        // + stage [96][132] f32 = 217152

__global__ __launch_bounds__(512, 1) void qkv_mma(
    const float* __restrict__ x,
    const float* __restrict__ bq, const float* __restrict__ bk,
    const float* __restrict__ bv)
{
    extern __shared__ __align__(16) unsigned char sm[];
    unsigned short* Xh = (unsigned short*)sm;           // [1156][72] fp16
    float* stage = (float*)(sm + QKV_HALO);             // [96][132] f32
    const int s = blockIdx.x, b = blockIdx.y;
    const int tid = threadIdx.x;
    const int wid = tid >> 5, lane = tid & 31;
    const int warpM = wid >> 2, warpN = wid & 3;
    const u32 sb = smem_u32(sm);

    // ---- full-frame halo fill (34x34x64) ----
    for (int i = tid; i < 34 * 34 * 64; i += 512) {
        int ic = i / 1156; int hw = i - ic * 1156;
        int h = hw / 34, w = hw - h * 34;
        int gh = h - 1, wi = w - 1;
        float v = 0.f;
        if ((unsigned)gh < 32u && (unsigned)wi < 32u)
            v = x[(((size_t)b * 64 + ic) * 64 + s) * 1024 + gh * 32 + wi];
        Xh[hw * 72 + ic] = us_hf(__float2half(v));
    }
    __syncthreads();

    const int kb_lane = ((lane >> 4) & 1) * 16;

    for (int strip = 0; strip < 8; strip++) {
        float acc[2][3][4];
#pragma unroll
        for (int mg = 0; mg < 2; mg++)
#pragma unroll
            for (int j = 0; j < 3; j++)
#pragma unroll
                for (int r = 0; r < 4; r++) acc[mg][j][r] = 0.f;

        int pr[2], pc[2];
#pragma unroll
        for (int mg = 0; mg < 2; mg++) {
            int p = strip * 128 + warpM * 32 + mg * 16 + ((lane >> 3) & 1) * 8 + (lane & 7);
            pr[mg] = p >> 5; pc[mg] = p & 31;
        }

        for (int dh = 0; dh < 3; dh++) {
#pragma unroll
            for (int dw = 0; dw < 3; dw++) {
                const int tap = dh * 3 + dw;
                u32 rowoff[2];
#pragma unroll
                for (int mg = 0; mg < 2; mg++)
                    rowoff[mg] = (u32)((pr[mg] + dh) * 34 + pc[mg] + dw) * 144;
                const uint4* bbase = g_Bfq + ((tap * 4) * 12 + warpN * 3) * 32 + lane;
#pragma unroll
                for (int ks = 0; ks < 4; ks++) {
                    uint4 B0 = bbase[ks * 12 * 32];
                    uint4 B1 = bbase[ks * 12 * 32 + 32];
                    uint4 B2 = bbase[ks * 12 * 32 + 64];
                    const u32 kbyte = (u32)ks * 32 + kb_lane;
#pragma unroll
                    for (int mg = 0; mg < 2; mg++) {
                        u32 a[4];
                        ldsm4(a, sb + rowoff[mg] + kbyte);
                        mma_fp16(acc[mg][0], a, B0.x, B0.y);
                        mma_fp16(acc[mg][0], a, B0.z, B0.w);
                        mma_fp16(acc[mg][1], a, B1.x, B1.y);
                        mma_fp16(acc[mg][1], a, B1.z, B1.w);
                        mma_fp16(acc[mg][2], a, B2.x, B2.y);
                        mma_fp16(acc[mg][2], a, B2.z, B2.w);
                    }
                }
            }
        }

        __syncthreads();   // prior strip's stage reads done
#pragma unroll
        for (int mg = 0; mg < 2; mg++)
#pragma unroll
            for (int j = 0; j < 3; j++)
#pragma unroll
                for (int r = 0; r < 4; r++) {
                    int n = warpN * 24 + j * 8 + (lane & 3) * 2 + (r & 1);
                    int m = warpM * 32 + mg * 16 + (lane >> 2) + ((r >> 1) & 1) * 8;
                    stage[n * 132 + m] = acc[mg][j][r];
                }
        __syncthreads();
        for (int i = tid; i < 96 * 64; i += 512) {
            int n = i >> 6, mp = (i & 63) * 2;
            float v0 = stage[n * 132 + mp];
            float v1 = stage[n * 132 + mp + 1];
            if (n < 32) {
                float bias = __ldg(bq + n);
                v0 += bias; v1 += bias;
                size_t o = (((size_t)b * 32 + n) * 64 + s) * 1024 + strip * 128 + mp;
                *(u32*)(g_qh + o) = hpack(v0, v1);
            } else if (n < 64) {
                int ch = n - 32;
                float bias = __ldg(bk + ch);
                v0 += bias; v1 += bias;
                unsigned short h0, l0, h1, l1;
                split_hf(v0, h0, l0); split_hf(v1, h1, l1);
                size_t o = (((size_t)b * 32 + ch) * 64 + s) * 1024 + strip * 128 + mp;
                *(u32*)(g_kh + o) = (u32)h0 | ((u32)h1 << 16);
                *(u32*)(g_kl + o) = (u32)l0 | ((u32)l1 << 16);
            } else {
                int ch = n - 64;
                float bias = __ldg(bv + ch);
                v0 += bias; v1 += bias;
                unsigned short h0, l0, h1, l1;
                split_hf(v0, h0, l0); split_hf(v1, h1, l1);
                size_t o = (((size_t)b * 32 + ch) * 64 + s) * 1024 + strip * 128 + mp;
                *(u32*)(g_vh + o) = (u32)h0 | ((u32)h1 << 16);
                *(u32*)(g_vl + o) = (u32)l0 | ((u32)l1 << 16);
            }
        }
    }
}

// ---------------------------------------------------------------------------
// Attention: fp16 2-pass (unchanged from R13-best).
// ---------------------------------------------------------------------------
#define ATT_AH   0
#define ATT_BUF  9216
#define ATT_STGA 27648
#define ATT_STGB 18432
#define ATT_SMEM (9216 + 2 * 27648)   // 64512

__global__ __launch_bounds__(256, 2) void attn_mma()
{
    extern __shared__ __align__(16) unsigned char sm[];
    const int bc = blockIdx.x;
    const int tid = threadIdx.x;
    const int wid = tid >> 5, lane = tid & 31;
    const int warpM = wid >> 2, warpN = wid & 3;   // 2 x 4
    const u32 sb = smem_u32(sm);
    const size_t gb = (size_t)bc * 65536;

    u32 a_rowoff[2];
#pragma unroll
    for (int mg = 0; mg < 2; mg++) {
        int p = warpM * 32 + mg * 16 + ((lane >> 3) & 1) * 8 + (lane & 7);
        a_rowoff[mg] = (u32)p * 144;
    }
    const u32 a_kb = ((lane >> 4) & 1) * 16;
    const int n0 = warpN * 16;
    const u32 b_rowoff = (u32)(n0 + (lane & 7) + ((lane >> 4) & 1) * 8) * 144;
    const u32 b_kb = ((lane >> 3) & 1) * 16;
    const int v_row = (lane & 7) + ((lane >> 3) & 1) * 8;
    const u32 v_fb = ((lane >> 4) & 1) * 16 + warpN * 32;

    auto issueA = [&](int f0, int stg) {
#pragma unroll
        for (int j = 0; j < 6; j++) {
            int idx = tid + j * 256;             // < 1536
            int plane = idx / 512;
            int r = (idx >> 3) & 63;
            int col = idx & 7;
            const unsigned short* src =
                (plane == 0) ? g_qh : (plane == 1) ? g_kh : g_kl;
            cpa16(sb + ATT_BUF + stg * ATT_STGA + plane * 9216 + r * 144 + col * 16,
                  src + gb + (size_t)r * 1024 + f0 + col * 8);
        }
        CPA_COMMIT();
    };

    float acc[2][2][4];
#pragma unroll
    for (int mg = 0; mg < 2; mg++)
#pragma unroll
        for (int nt = 0; nt < 2; nt++)
#pragma unroll
            for (int r = 0; r < 4; r++) acc[mg][nt][r] = 0.f;

    issueA(0, 0);
    CPA_WAIT0();
    __syncthreads();
    for (int c = 0; c < 16; c++) {
        if (c + 1 < 16) issueA((c + 1) * 64, (c + 1) & 1);
        const u32 base = sb + ATT_BUF + (c & 1) * ATT_STGA;
#pragma unroll
        for (int ks = 0; ks < 4; ks++) {
            u32 bh[4], bl[4];
            ldsm4(bh, base + 9216 + b_rowoff + ks * 32 + b_kb);
            ldsm4(bl, base + 18432 + b_rowoff + ks * 32 + b_kb);
#pragma unroll
            for (int mg = 0; mg < 2; mg++) {
                u32 ah[4];
                ldsm4(ah, base + a_rowoff[mg] + ks * 32 + a_kb);
                mma_fp16(acc[mg][0], ah, bh[0], bh[1]);
                mma_fp16(acc[mg][0], ah, bl[0], bl[1]);
                mma_fp16(acc[mg][1], ah, bh[2], bh[3]);
                mma_fp16(acc[mg][1], ah, bl[2], bl[3]);
            }
        }
        if (c + 1 < 16) { CPA_WAIT0(); __syncthreads(); }
    }

    unsigned short* Ah = (unsigned short*)(sm + ATT_AH);
#pragma unroll
    for (int mg = 0; mg < 2; mg++)
#pragma unroll
        for (int nt = 0; nt < 2; nt++)
#pragma unroll
            for (int half = 0; half < 2; half++) {
                int row = warpM * 32 + mg * 16 + (lane >> 2) + half * 8;
                int n = n0 + nt * 8 + (lane & 3) * 2;
                float z0 = acc[mg][nt][half * 2 + 0] * 0.03125f;
                float z1 = acc[mg][nt][half * 2 + 1] * 0.03125f;
                float a0 = 1.f / (1.f + __expf(-z0));
                float a1 = 1.f / (1.f + __expf(-z1));
                *(u32*)(Ah + row * 72 + n) = hpack(a0, a1);
            }

    auto issueB = [&](int f0, int stg) {
#pragma unroll
        for (int j = 0; j < 4; j++) {
            int idx = tid + j * 256;             // < 1024
            int plane = idx >> 9;
            int r = (idx >> 3) & 63;
            int col = idx & 7;
            const unsigned short* src = (plane == 0) ? g_vh : g_vl;
            cpa16(sb + ATT_BUF + stg * ATT_STGB + plane * 9216 + r * 144 + col * 16,
                  src + gb + (size_t)r * 1024 + f0 + col * 8);
        }
        CPA_COMMIT();
    };

    issueB(0, 0);
    CPA_WAIT0();
    __syncthreads();

    for (int c = 0; c < 16; c++) {
        if (c + 1 < 16) issueB((c + 1) * 64, (c + 1) & 1);
        const u32 base = sb + ATT_BUF + (c & 1) * ATT_STGB;
        float oa[2][2][4];
#pragma unroll
        for (int mg = 0; mg < 2; mg++)
#pragma unroll
            for (int nt = 0; nt < 2; nt++)
#pragma unroll
                for (int r = 0; r < 4; r++) oa[mg][nt][r] = 0.f;
#pragma unroll
        for (int ks = 0; ks < 4; ks++) {
            u32 vh[4], vl[4];
            ldsm4t(vh, base + (u32)(ks * 16 + v_row) * 144 + v_fb);
            ldsm4t(vl, base + 9216 + (u32)(ks * 16 + v_row) * 144 + v_fb);
#pragma unroll
            for (int mg = 0; mg < 2; mg++) {
                u32 ah[4];
                ldsm4(ah, sb + ATT_AH + a_rowoff[mg] + ks * 32 + a_kb);
                mma_fp16(oa[mg][0], ah, vh[0], vh[1]);
                mma_fp16(oa[mg][0], ah, vl[0], vl[1]);
                mma_fp16(oa[mg][1], ah, vh[2], vh[3]);
                mma_fp16(oa[mg][1], ah, vl[2], vl[3]);
            }
        }
        const int f0 = c * 64;
#pragma unroll
        for (int mg = 0; mg < 2; mg++)
#pragma unroll
            for (int nt = 0; nt < 2; nt++)
#pragma unroll
                for (int half = 0; half < 2; half++) {
                    int row = warpM * 32 + mg * 16 + (lane >> 2) + half * 8;
                    int f = f0 + warpN * 16 + nt * 8 + (lane & 3) * 2;
                    size_t o = gb + (size_t)row * 1024 + f;
                    *(u32*)(g_aoh + o) =
                        hpack(oa[mg][nt][half * 2 + 0], oa[mg][nt][half * 2 + 1]);
                }
        if (c + 1 < 16) { CPA_WAIT0(); __syncthreads(); }
    }
}

// ---------------------------------------------------------------------------
// oconv: full-frame block.  Grid (64 s, 16 b), 512 threads.
// Halo [1156][40] fp16 resident; 8 strips; warp tile 32 x 16 (2 m16 x 2 n8).
// ---------------------------------------------------------------------------
#define OC_HALO   92480                     // 1156 * 80 B
#define OCONV_SMEM (OC_HALO + 33792)        // + stage [64][132] f32 = 126272

__global__ __launch_bounds__(512, 1) void oconv_mma(
    const float* __restrict__ bo, float* __restrict__ out)
{
    extern __shared__ __align__(16) unsigned char sm[];
    unsigned short* Xh = (unsigned short*)sm;           // [1156][40] fp16
    float* stage = (float*)(sm + OC_HALO);              // [64][132] f32
    const int s = blockIdx.x, b = blockIdx.y;
    const int tid = threadIdx.x;
    const int wid = tid >> 5, lane = tid & 31;
    const int warpM = wid >> 2, warpN = wid & 3;
    const u32 sb = smem_u32(sm);

    for (int i = tid; i < 34 * 34 * 32; i += 512) {
        int ic = i / 1156; int hw = i - ic * 1156;
        int h = hw / 34, w = hw - h * 34;
        int gh = h - 1, wi = w - 1;
        unsigned short v = 0;
        if ((unsigned)gh < 32u && (unsigned)wi < 32u)
            v = g_aoh[(((size_t)b * 32 + ic) * 64 + s) * 1024 + gh * 32 + wi];
        Xh[hw * 40 + ic] = v;
    }
    __syncthreads();

    const int kb_lane = ((lane >> 4) & 1) * 16;

    for (int strip = 0; strip < 8; strip++) {
        float acc[2][2][4];
#pragma unroll
        for (int mg = 0; mg < 2; mg++)
#pragma unroll
            for (int j = 0; j < 2; j++)
#pragma unroll
                for (int r = 0; r < 4; r++) acc[mg][j][r] = 0.f;

        int pr[2], pc[2];
#pragma unroll
        for (int mg = 0; mg < 2; mg++) {
            int p = strip * 128 + warpM * 32 + mg * 16 + ((lane >> 3) & 1) * 8 + (lane & 7);
            pr[mg] = p >> 5; pc[mg] = p & 31;
        }

        for (int dh = 0; dh < 3; dh++) {
#pragma unroll
            for (int dw = 0; dw < 3; dw++) {
                const int tap = dh * 3 + dw;
                u32 rowoff[2];
#pragma unroll
                for (int mg = 0; mg < 2; mg++)
                    rowoff[mg] = (u32)((pr[mg] + dh) * 34 + pc[mg] + dw) * 80;
                const uint4* bbase = g_Bfo + ((tap * 2) * 8 + warpN * 2) * 32 + lane;
#pragma unroll
                for (int ks = 0; ks < 2; ks++) {
                    uint4 B0 = bbase[ks * 8 * 32];
                    uint4 B1 = bbase[ks * 8 * 32 + 32];
                    const u32 kbyte = (u32)ks * 32 + kb_lane;
#pragma unroll
                    for (int mg = 0; mg < 2; mg++) {
                        u32 a[4];
                        ldsm4(a, sb + rowoff[mg] + kbyte);
                        mma_fp16(acc[mg][0], a, B0.x, B0.y);
                        mma_fp16(acc[mg][0], a, B0.z, B0.w);
                        mma_fp16(acc[mg][1], a, B1.x, B1.y);
                        mma_fp16(acc[mg][1], a, B1.z, B1.w);
                    }
                }
            }
        }

        __syncthreads();
#pragma unroll
        for (int mg = 0; mg < 2; mg++)
#pragma unroll
            for (int j = 0; j < 2; j++)
#pragma unroll
                for (int r = 0; r < 4; r++) {
                    int n = warpN * 16 + j * 8 + (lane & 3) * 2 + (r & 1);
                    int m = warpM * 32 + mg * 16 + (lane >> 2) + ((r >> 1) & 1) * 8;
                    stage[n * 132 + m] = acc[mg][j][r];
                }
        __syncthreads();
        for (int i = tid; i < 64 * 128; i += 512) {
            int n = i >> 7, m = i & 127;
            float v = stage[n * 132 + m] + __ldg(bo + n);
            out[(((size_t)b * 64 + n) * 64 + s) * 1024 + strip * 128 + m] = v;
        }
    }
}

// ---------------------------------------------------------------------------
// kernel_launch
// ---------------------------------------------------------------------------
extern "C" void kernel_launch(void* const* d_in, const int* in_sizes, int n_in,
                              void* d_out, int out_size) {
    const float* x  = (const float*)d_in[0];
    const float* wq = (const float*)d_in[1];
    const float* bq = (const float*)d_in[2];
    const float* wk = (const float*)d_in[3];
    const float* bk = (const float*)d_in[4];
    const float* wv = (const float*)d_in[5];
    const float* bv = (const float*)d_in[6];
    const float* wo = (const float*)d_in[7];
    const float* bo = (const float*)d_in[8];
    float* out = (float*)d_out;

    static int configured = 0;
    if (!configured) {
        cudaFuncSetAttribute(qkv_mma, cudaFuncAttributeMaxDynamicSharedMemorySize, QKV_SMEM);
        cudaFuncSetAttribute(attn_mma, cudaFuncAttributeMaxDynamicSharedMemorySize, ATT_SMEM);
        cudaFuncSetAttribute(oconv_mma, cudaFuncAttributeMaxDynamicSharedMemorySize, OCONV_SMEM);
        configured = 1;
    }

    pack_qkv_frag<<<(9 * 4 * 12 * 32 + 255) / 256, 256>>>(wq, wk, wv);
    pack_o_frag<<<(9 * 2 * 8 * 32 + 255) / 256, 256>>>(wo);

    dim3 fgrid(64, 16);
    qkv_mma<<<fgrid, 512, QKV_SMEM>>>(x, bq, bk, bv);
    attn_mma<<<512, 256, ATT_SMEM>>>();
    oconv_mma<<<fgrid, 512, OCONV_SMEM>>>(bo, out);
}

// round 16
// speedup vs baseline: 1.3690x; 1.3690x over previous
#include <cuda_runtime.h>
#include <cuda_bf16.h>
#include <cuda_fp16.h>

typedef unsigned long long ull;
typedef unsigned int u32;

// ---------------------------------------------------------------------------
// Scratch planes (fp16): q single, k/v hi+lo, attn-out single
// ---------------------------------------------------------------------------
#define PLANE_ELEMS 33554432
static __device__ unsigned short g_qh[PLANE_ELEMS];
static __device__ unsigned short g_kh[PLANE_ELEMS], g_kl[PLANE_ELEMS];
static __device__ unsigned short g_vh[PLANE_ELEMS], g_vl[PLANE_ELEMS];
static __device__ unsigned short g_aoh[PLANE_ELEMS];

// B fragments (fp16 hi only), mma.sync fragment order, tap-major.
static __device__ __align__(16) uint2 g_Bfq[9 * 4 * 12 * 32];
static __device__ __align__(16) uint2 g_Bfo[9 * 2 * 8 * 32];

// ---------------------------------------------------------------------------
// helpers
// ---------------------------------------------------------------------------
__device__ __forceinline__ u32 smem_u32(const void* p) {
    u32 a;
    asm("{ .reg .u64 t; cvta.to.shared.u64 t, %1; cvt.u32.u64 %0, t; }" : "=r"(a) : "l"(p));
    return a;
}
__device__ __forceinline__ unsigned short us_hf(__half h) {
    return *reinterpret_cast<unsigned short*>(&h);
}
__device__ __forceinline__ void split_hf(float v, unsigned short& h, unsigned short& l) {
    __half hb = __float2half(v);
    h = us_hf(hb);
    l = us_hf(__float2half(v - __half2float(hb)));
}
__device__ __forceinline__ u32 hpack(float a, float b) {
    __half2 h = __floats2half2_rn(a, b);
    return *reinterpret_cast<u32*>(&h);
}
__device__ __forceinline__ void ldsm4(u32* r, u32 addr) {
    asm volatile("ldmatrix.sync.aligned.m8n8.x4.shared.b16 {%0,%1,%2,%3}, [%4];"
                 : "=r"(r[0]), "=r"(r[1]), "=r"(r[2]), "=r"(r[3]) : "r"(addr));
}
__device__ __forceinline__ void ldsm4t(u32* r, u32 addr) {
    asm volatile("ldmatrix.sync.aligned.m8n8.x4.trans.shared.b16 {%0,%1,%2,%3}, [%4];"
                 : "=r"(r[0]), "=r"(r[1]), "=r"(r[2]), "=r"(r[3]) : "r"(addr));
}
__device__ __forceinline__ void mma_fp16(float* c, const u32* a, u32 b0, u32 b1) {
    asm volatile(
        "mma.sync.aligned.m16n8k16.row.col.f32.f16.f16.f32 "
        "{%0,%1,%2,%3}, {%4,%5,%6,%7}, {%8,%9}, {%0,%1,%2,%3};"
        : "+f"(c[0]), "+f"(c[1]), "+f"(c[2]), "+f"(c[3])
        : "r"(a[0]), "r"(a[1]), "r"(a[2]), "r"(a[3]), "r"(b0), "r"(b1));
}
__device__ __forceinline__ void cpa16(u32 dst, const void* src) {
    asm volatile("cp.async.cg.shared.global [%0], [%1], 16;" :: "r"(dst), "l"(src));
}
#define CPA_COMMIT() asm volatile("cp.async.commit_group;" ::: "memory")
#define CPA_WAIT0()  asm volatile("cp.async.wait_group 0;" ::: "memory")

// ---------------------------------------------------------------------------
// Weight fragment pre-pack (fp16 hi only)
// ---------------------------------------------------------------------------
__global__ void pack_qkv_frag(const float* __restrict__ wq, const float* __restrict__ wk,
                              const float* __restrict__ wv)
{
    int idx = blockIdx.x * 256 + threadIdx.x;
    if (idx >= 9 * 4 * 12 * 32) return;
    int lane = idx & 31; int t = idx >> 5;
    int n8 = t % 12; t /= 12;
    int ks = t & 3;  int tap = t >> 2;
    int dh = tap / 3, dw = tap % 3;
    int n = n8 * 8 + (lane >> 2);
    const float* src = (n < 32) ? wq + n * 576
                     : (n < 64) ? wk + (n - 32) * 576
                                : wv + (n - 64) * 576;
    u32 u[2];
#pragma unroll
    for (int r = 0; r < 2; r++) {
        int ic0 = ks * 16 + r * 8 + (lane & 3) * 2;
        float w0 = src[ic0 * 9 + dh * 3 + dw];
        float w1 = src[(ic0 + 1) * 9 + dh * 3 + dw];
        u[r] = hpack(w0, w1);
    }
    g_Bfq[idx] = make_uint2(u[0], u[1]);
}

__global__ void pack_o_frag(const float* __restrict__ wo)
{
    int idx = blockIdx.x * 256 + threadIdx.x;
    if (idx >= 9 * 2 * 8 * 32) return;
    int lane = idx & 31; int t = idx >> 5;
    int n8 = t & 7; t >>= 3;
    int ks = t & 1;  int tap = t >> 1;
    int dh = tap / 3, dw = tap % 3;
    int n = n8 * 8 + (lane >> 2);
    const float* src = wo + n * 288;
    u32 u[2];
#pragma unroll
    for (int r = 0; r < 2; r++) {
        int ic0 = ks * 16 + r * 8 + (lane & 3) * 2;
        float w0 = src[ic0 * 9 + dh * 3 + dw];
        float w1 = src[(ic0 + 1) * 9 + dh * 3 + dw];
        u[r] = hpack(w0, w1);
    }
    g_Bfo[idx] = make_uint2(u[0], u[1]);
}

// ---------------------------------------------------------------------------
// qkv conv: fp16 single-pass, dh-outer / dw-unrolled.  (R13 structure)
// ---------------------------------------------------------------------------
#define QKV_SMEM 50688

__global__ __launch_bounds__(256, 2) void qkv_mma(
    const float* __restrict__ x,
    const float* __restrict__ bq, const float* __restrict__ bk,
    const float* __restrict__ bv)
{
    extern __shared__ __align__(16) unsigned char sm[];
    unsigned short* Xh = (unsigned short*)sm;            // [6][34][72] fp16
    const int strip = blockIdx.x, s = blockIdx.y, b = blockIdx.z;
    const int tid = threadIdx.x;
    const int wid = tid >> 5, lane = tid & 31;
    const int warpM = wid >> 2, warpN = wid & 3;
    const u32 sb = smem_u32(sm);

    for (int i = tid; i < 6 * 34 * 64; i += 256) {
        int ic = i / 204; int rem = i - ic * 204;
        int h = rem / 34, w = rem - h * 34;
        int gh = strip * 4 + h - 1, wi = w - 1;
        float v = 0.f;
        if ((unsigned)gh < 32u && (unsigned)wi < 32u)
            v = x[(((size_t)b * 64 + ic) * 64 + s) * 1024 + gh * 32 + wi];
        Xh[(h * 34 + w) * 72 + ic] = us_hf(__float2half(v));
    }
    __syncthreads();

    float acc[4][3][4];
#pragma unroll
    for (int mg = 0; mg < 4; mg++)
#pragma unroll
        for (int j = 0; j < 3; j++)
#pragma unroll
            for (int r = 0; r < 4; r++) acc[mg][j][r] = 0.f;

    const int kb_lane = ((lane >> 4) & 1) * 16;
    int pr[4], pc[4];
#pragma unroll
    for (int mg = 0; mg < 4; mg++) {
        int p = warpM * 64 + mg * 16 + ((lane >> 3) & 1) * 8 + (lane & 7);
        pr[mg] = p >> 5; pc[mg] = p & 31;
    }

    for (int dh = 0; dh < 3; dh++) {
#pragma unroll
        for (int dw = 0; dw < 3; dw++) {
            const int tap = dh * 3 + dw;
            u32 rowoff[4];
#pragma unroll
            for (int mg = 0; mg < 4; mg++)
                rowoff[mg] = (u32)((pr[mg] + dh) * 34 + pc[mg] + dw) * 144;
            const uint2* bbase = g_Bfq + ((tap * 4) * 12 + warpN * 3) * 32 + lane;
#pragma unroll
            for (int ks = 0; ks < 4; ks++) {
                uint2 B0 = bbase[ks * 12 * 32];
                uint2 B1 = bbase[ks * 12 * 32 + 32];
                uint2 B2 = bbase[ks * 12 * 32 + 64];
                const u32 kbyte = (u32)ks * 32 + kb_lane;
#pragma unroll
                for (int mg = 0; mg < 4; mg++) {
                    u32 a[4];
                    ldsm4(a, sb + rowoff[mg] + kbyte);
                    mma_fp16(acc[mg][0], a, B0.x, B0.y);
                    mma_fp16(acc[mg][1], a, B1.x, B1.y);
                    mma_fp16(acc[mg][2], a, B2.x, B2.y);
                }
            }
        }
    }

    __syncthreads();
    float* stage = (float*)sm;                       // [96][132]
#pragma unroll
    for (int mg = 0; mg < 4; mg++)
#pragma unroll
        for (int j = 0; j < 3; j++)
#pragma unroll
            for (int r = 0; r < 4; r++) {
                int n = warpN * 24 + j * 8 + (lane & 3) * 2 + (r & 1);
                int m = warpM * 64 + mg * 16 + (lane >> 2) + ((r >> 1) & 1) * 8;
                stage[n * 132 + m] = acc[mg][j][r];
            }
    __syncthreads();
    for (int i = tid; i < 96 * 64; i += 256) {
        int n = i >> 6, mp = (i & 63) * 2;
        float v0 = stage[n * 132 + mp];
        float v1 = stage[n * 132 + mp + 1];
        if (n < 32) {
            float bias = __ldg(bq + n);
            v0 += bias; v1 += bias;
            size_t o = (((size_t)b * 32 + n) * 64 + s) * 1024 + strip * 128 + mp;
            *(u32*)(g_qh + o) = hpack(v0, v1);
        } else if (n < 64) {
            int ch = n - 32;
            float bias = __ldg(bk + ch);
            v0 += bias; v1 += bias;
            unsigned short h0, l0, h1, l1;
            split_hf(v0, h0, l0); split_hf(v1, h1, l1);
            size_t o = (((size_t)b * 32 + ch) * 64 + s) * 1024 + strip * 128 + mp;
            *(u32*)(g_kh + o) = (u32)h0 | ((u32)h1 << 16);
            *(u32*)(g_kl + o) = (u32)l0 | ((u32)l1 << 16);
        } else {
            int ch = n - 64;
            float bias = __ldg(bv + ch);
            v0 += bias; v1 += bias;
            unsigned short h0, l0, h1, l1;
            split_hf(v0, h0, l0); split_hf(v1, h1, l1);
            size_t o = (((size_t)b * 32 + ch) * 64 + s) * 1024 + strip * 128 + mp;
            *(u32*)(g_vh + o) = (u32)h0 | ((u32)h1 << 16);
            *(u32*)(g_vl + o) = (u32)l0 | ((u32)l1 << 16);
        }
    }
}

// ---------------------------------------------------------------------------
// Attention: fp16 2-pass (unchanged, R13-best).
// ---------------------------------------------------------------------------
#define ATT_AH   0
#define ATT_BUF  9216
#define ATT_STGA 27648
#define ATT_STGB 18432
#define ATT_SMEM (9216 + 2 * 27648)   // 64512

__global__ __launch_bounds__(256, 2) void attn_mma()
{
    extern __shared__ __align__(16) unsigned char sm[];
    const int bc = blockIdx.x;
    const int tid = threadIdx.x;
    const int wid = tid >> 5, lane = tid & 31;
    const int warpM = wid >> 2, warpN = wid & 3;   // 2 x 4
    const u32 sb = smem_u32(sm);
    const size_t gb = (size_t)bc * 65536;

    u32 a_rowoff[2];
#pragma unroll
    for (int mg = 0; mg < 2; mg++) {
        int p = warpM * 32 + mg * 16 + ((lane >> 3) & 1) * 8 + (lane & 7);
        a_rowoff[mg] = (u32)p * 144;
    }
    const u32 a_kb = ((lane >> 4) & 1) * 16;
    const int n0 = warpN * 16;
    const u32 b_rowoff = (u32)(n0 + (lane & 7) + ((lane >> 4) & 1) * 8) * 144;
    const u32 b_kb = ((lane >> 3) & 1) * 16;
    const int v_row = (lane & 7) + ((lane >> 3) & 1) * 8;
    const u32 v_fb = ((lane >> 4) & 1) * 16 + warpN * 32;

    auto issueA = [&](int f0, int stg) {
#pragma unroll
        for (int j = 0; j < 6; j++) {
            int idx = tid + j * 256;             // < 1536
            int plane = idx / 512;
            int r = (idx >> 3) & 63;
            int col = idx & 7;
            const unsigned short* src =
                (plane == 0) ? g_qh : (plane == 1) ? g_kh : g_kl;
            cpa16(sb + ATT_BUF + stg * ATT_STGA + plane * 9216 + r * 144 + col * 16,
                  src + gb + (size_t)r * 1024 + f0 + col * 8);
        }
        CPA_COMMIT();
    };

    float acc[2][2][4];
#pragma unroll
    for (int mg = 0; mg < 2; mg++)
#pragma unroll
        for (int nt = 0; nt < 2; nt++)
#pragma unroll
            for (int r = 0; r < 4; r++) acc[mg][nt][r] = 0.f;

    issueA(0, 0);
    CPA_WAIT0();
    __syncthreads();
    for (int c = 0; c < 16; c++) {
        if (c + 1 < 16) issueA((c + 1) * 64, (c + 1) & 1);
        const u32 base = sb + ATT_BUF + (c & 1) * ATT_STGA;
#pragma unroll
        for (int ks = 0; ks < 4; ks++) {
            u32 bh[4], bl[4];
            ldsm4(bh, base + 9216 + b_rowoff + ks * 32 + b_kb);
            ldsm4(bl, base + 18432 + b_rowoff + ks * 32 + b_kb);
#pragma unroll
            for (int mg = 0; mg < 2; mg++) {
                u32 ah[4];
                ldsm4(ah, base + a_rowoff[mg] + ks * 32 + a_kb);
                mma_fp16(acc[mg][0], ah, bh[0], bh[1]);
                mma_fp16(acc[mg][0], ah, bl[0], bl[1]);
                mma_fp16(acc[mg][1], ah, bh[2], bh[3]);
                mma_fp16(acc[mg][1], ah, bl[2], bl[3]);
            }
        }
        if (c + 1 < 16) { CPA_WAIT0(); __syncthreads(); }
    }

    unsigned short* Ah = (unsigned short*)(sm + ATT_AH);
#pragma unroll
    for (int mg = 0; mg < 2; mg++)
#pragma unroll
        for (int nt = 0; nt < 2; nt++)
#pragma unroll
            for (int half = 0; half < 2; half++) {
                int row = warpM * 32 + mg * 16 + (lane >> 2) + half * 8;
                int n = n0 + nt * 8 + (lane & 3) * 2;
                float z0 = acc[mg][nt][half * 2 + 0] * 0.03125f;
                float z1 = acc[mg][nt][half * 2 + 1] * 0.03125f;
                float a0 = 1.f / (1.f + __expf(-z0));
                float a1 = 1.f / (1.f + __expf(-z1));
                *(u32*)(Ah + row * 72 + n) = hpack(a0, a1);
            }

    auto issueB = [&](int f0, int stg) {
#pragma unroll
        for (int j = 0; j < 4; j++) {
            int idx = tid + j * 256;             // < 1024
            int plane = idx >> 9;
            int r = (idx >> 3) & 63;
            int col = idx & 7;
            const unsigned short* src = (plane == 0) ? g_vh : g_vl;
            cpa16(sb + ATT_BUF + stg * ATT_STGB + plane * 9216 + r * 144 + col * 16,
                  src + gb + (size_t)r * 1024 + f0 + col * 8);
        }
        CPA_COMMIT();
    };

    issueB(0, 0);
    CPA_WAIT0();
    __syncthreads();   // A plane visible + V0 ready

    for (int c = 0; c < 16; c++) {
        if (c + 1 < 16) issueB((c + 1) * 64, (c + 1) & 1);
        const u32 base = sb + ATT_BUF + (c & 1) * ATT_STGB;
        float oa[2][2][4];
#pragma unroll
        for (int mg = 0; mg < 2; mg++)
#pragma unroll
            for (int nt = 0; nt < 2; nt++)
#pragma unroll
                for (int r = 0; r < 4; r++) oa[mg][nt][r] = 0.f;
#pragma unroll
        for (int ks = 0; ks < 4; ks++) {
            u32 vh[4], vl[4];
            ldsm4t(vh, base + (u32)(ks * 16 + v_row) * 144 + v_fb);
            ldsm4t(vl, base + 9216 + (u32)(ks * 16 + v_row) * 144 + v_fb);
#pragma unroll
            for (int mg = 0; mg < 2; mg++) {
                u32 ah[4];
                ldsm4(ah, sb + ATT_AH + a_rowoff[mg] + ks * 32 + a_kb);
                mma_fp16(oa[mg][0], ah, vh[0], vh[1]);
                mma_fp16(oa[mg][0], ah, vl[0], vl[1]);
                mma_fp16(oa[mg][1], ah, vh[2], vh[3]);
                mma_fp16(oa[mg][1], ah, vl[2], vl[3]);
            }
        }
        const int f0 = c * 64;
#pragma unroll
        for (int mg = 0; mg < 2; mg++)
#pragma unroll
            for (int nt = 0; nt < 2; nt++)
#pragma unroll
                for (int half = 0; half < 2; half++) {
                    int row = warpM * 32 + mg * 16 + (lane >> 2) + half * 8;
                    int f = f0 + warpN * 16 + nt * 8 + (lane & 3) * 2;
                    size_t o = gb + (size_t)row * 1024 + f;
                    *(u32*)(g_aoh + o) =
                        hpack(oa[mg][nt][half * 2 + 0], oa[mg][nt][half * 2 + 1]);
                }
        if (c + 1 < 16) { CPA_WAIT0(); __syncthreads(); }
    }
}

// ---------------------------------------------------------------------------
// oconv: fp16 single-pass; halo raw fp16 copy.  (R13 structure)
// ---------------------------------------------------------------------------
#define OCONV_SMEM 33792

__global__ __launch_bounds__(256, 2) void oconv_mma(
    const float* __restrict__ bo, float* __restrict__ out)
{
    extern __shared__ __align__(16) unsigned char sm[];
    unsigned short* Xh = (unsigned short*)sm;            // [6][34][40]
    const int strip = blockIdx.x, s = blockIdx.y, b = blockIdx.z;
    const int tid = threadIdx.x;
    const int wid = tid >> 5, lane = tid & 31;
    const int warpM = wid >> 2, warpN = wid & 3;
    const u32 sb = smem_u32(sm);

    for (int i = tid; i < 6 * 34 * 32; i += 256) {
        int ic = i / 204; int rem = i - ic * 204;
        int h = rem / 34, w = rem - h * 34;
        int gh = strip * 4 + h - 1, wi = w - 1;
        unsigned short v = 0;
        if ((unsigned)gh < 32u && (unsigned)wi < 32u)
            v = g_aoh[(((size_t)b * 32 + ic) * 64 + s) * 1024 + gh * 32 + wi];
        Xh[(h * 34 + w) * 40 + ic] = v;
    }
    __syncthreads();

    float acc[4][2][4];
#pragma unroll
    for (int mg = 0; mg < 4; mg++)
#pragma unroll
        for (int j = 0; j < 2; j++)
#pragma unroll
            for (int r = 0; r < 4; r++) acc[mg][j][r] = 0.f;

    const int kb_lane = ((lane >> 4) & 1) * 16;
    int pr[4], pc[4];
#pragma unroll
    for (int mg = 0; mg < 4; mg++) {
        int p = warpM * 64 + mg * 16 + ((lane >> 3) & 1) * 8 + (lane & 7);
        pr[mg] = p >> 5; pc[mg] = p & 31;
    }

    for (int dh = 0; dh < 3; dh++) {
#pragma unroll
        for (int dw = 0; dw < 3; dw++) {
            const int tap = dh * 3 + dw;
            u32 rowoff[4];
#pragma unroll
            for (int mg = 0; mg < 4; mg++)
                rowoff[mg] = (u32)((pr[mg] + dh) * 34 + pc[mg] + dw) * 80;
            const uint2* bbase = g_Bfo + ((tap * 2) * 8 + warpN * 2) * 32 + lane;
#pragma unroll
            for (int ks = 0; ks < 2; ks++) {
                uint2 B0 = bbase[ks * 8 * 32];
                uint2 B1 = bbase[ks * 8 * 32 + 32];
                const u32 kbyte = (u32)ks * 32 + kb_lane;
#pragma unroll
                for (int mg = 0; mg < 4; mg++) {
                    u32 a[4];
                    ldsm4(a, sb + rowoff[mg] + kbyte);
                    mma_fp16(acc[mg][0], a, B0.x, B0.y);
                    mma_fp16(acc[mg][1], a, B1.x, B1.y);
                }
            }
        }
    }

    __syncthreads();
    float* stage = (float*)sm;                       // [64][132]
#pragma unroll
    for (int mg = 0; mg < 4; mg++)
#pragma unroll
        for (int j = 0; j < 2; j++)
#pragma unroll
            for (int r = 0; r < 4; r++) {
                int n = warpN * 16 + j * 8 + (lane & 3) * 2 + (r & 1);
                int m = warpM * 64 + mg * 16 + (lane >> 2) + ((r >> 1) & 1) * 8;
                stage[n * 132 + m] = acc[mg][j][r];
            }
    __syncthreads();
    for (int i = tid; i < 64 * 128; i += 256) {
        int n = i >> 7, m = i & 127;
        float v = stage[n * 132 + m] + __ldg(bo + n);
        out[(((size_t)b * 64 + n) * 64 + s) * 1024 + strip * 128 + m] = v;
    }
}

// ---------------------------------------------------------------------------
// kernel_launch
// ---------------------------------------------------------------------------
extern "C" void kernel_launch(void* const* d_in, const int* in_sizes, int n_in,
                              void* d_out, int out_size) {
    const float* x  = (const float*)d_in[0];
    const float* wq = (const float*)d_in[1];
    const float* bq = (const float*)d_in[2];
    const float* wk = (const float*)d_in[3];
    const float* bk = (const float*)d_in[4];
    const float* wv = (const float*)d_in[5];
    const float* bv = (const float*)d_in[6];
    const float* wo = (const float*)d_in[7];
    const float* bo = (const float*)d_in[8];
    float* out = (float*)d_out;

    static int configured = 0;
    if (!configured) {
        cudaFuncSetAttribute(qkv_mma, cudaFuncAttributeMaxDynamicSharedMemorySize, QKV_SMEM);
        cudaFuncSetAttribute(attn_mma, cudaFuncAttributeMaxDynamicSharedMemorySize, ATT_SMEM);
        cudaFuncSetAttribute(oconv_mma, cudaFuncAttributeMaxDynamicSharedMemorySize, OCONV_SMEM);
        configured = 1;
    }

    pack_qkv_frag<<<(9 * 4 * 12 * 32 + 255) / 256, 256>>>(wq, wk, wv);
    pack_o_frag<<<(9 * 2 * 8 * 32 + 255) / 256, 256>>>(wo);

    dim3 cgrid(8, 64, 16);
    qkv_mma<<<cgrid, 256, QKV_SMEM>>>(x, bq, bk, bv);
    attn_mma<<<512, 256, ATT_SMEM>>>();
    oconv_mma<<<cgrid, 256, OCONV_SMEM>>>(bo, out);
}